// round 9
// baseline (speedup 1.0000x reference)
#include <cuda_runtime.h>
#include <cuda_fp16.h>
#include <math.h>

#define NNODES 100000
#define EDGES  3200000
#define HDIM   128
#define EDIM   16
#define PTYPES 6

// ---- __device__ scratch (allocations are banned) ----
__device__ int    g_cnt[NNODES];
__device__ int    g_rowptr[NNODES + 1];
__device__ int    g_rowpos[NNODES];
__device__ int    g_col_s[EDGES];       // CSR-ordered packed (col | ptype<<24)
__device__ __half g_kh[NNODES * HDIM];  // fp16 k     (25.6 MB)
__device__ __half g_vh[NNODES * HDIM];  // fp16 v     (25.6 MB)
__device__ __half g_eh[NNODES * EDIM];  // fp16 eigs   (3.2 MB)
__device__ float  g_pexp[PTYPES];
__device__ float  g_expl;

// ---------------------------------------------------------------------------
// 0) prep: zero histogram, exp tables, fp16 copies of k, v, eigs
// ---------------------------------------------------------------------------
__global__ void k_prep(const float* __restrict__ k,
                       const float* __restrict__ v,
                       const float* __restrict__ eigs,
                       const float* __restrict__ lambda0,
                       const float* __restrict__ path_w, int n_nodes) {
    int tid = blockIdx.x * blockDim.x + threadIdx.x;
    int stride = gridDim.x * blockDim.x;

    for (int i = tid; i < n_nodes; i += stride) g_cnt[i] = 0;

    int nk4 = n_nodes * (HDIM / 4);
    for (int i = tid; i < nk4; i += stride) {
        float4 f = __ldg(reinterpret_cast<const float4*>(k) + i);
        __half2 lo = __floats2half2_rn(f.x, f.y);
        __half2 hi = __floats2half2_rn(f.z, f.w);
        uint2 o;
        o.x = *reinterpret_cast<unsigned*>(&lo);
        o.y = *reinterpret_cast<unsigned*>(&hi);
        reinterpret_cast<uint2*>(g_kh)[i] = o;
    }
    for (int i = tid; i < nk4; i += stride) {
        float4 f = __ldg(reinterpret_cast<const float4*>(v) + i);
        __half2 lo = __floats2half2_rn(f.x, f.y);
        __half2 hi = __floats2half2_rn(f.z, f.w);
        uint2 o;
        o.x = *reinterpret_cast<unsigned*>(&lo);
        o.y = *reinterpret_cast<unsigned*>(&hi);
        reinterpret_cast<uint2*>(g_vh)[i] = o;
    }
    int ne4 = n_nodes * (EDIM / 4);
    for (int i = tid; i < ne4; i += stride) {
        float4 f = __ldg(reinterpret_cast<const float4*>(eigs) + i);
        __half2 lo = __floats2half2_rn(f.x, f.y);
        __half2 hi = __floats2half2_rn(f.z, f.w);
        uint2 o;
        o.x = *reinterpret_cast<unsigned*>(&lo);
        o.y = *reinterpret_cast<unsigned*>(&hi);
        reinterpret_cast<uint2*>(g_eh)[i] = o;
    }

    if (tid < PTYPES) g_pexp[tid] = expf(path_w[tid]);
    if (tid == 0)     g_expl = expf(lambda0[0]);
}

// ---------------------------------------------------------------------------
// 1) histogram of destination rows — 8 edges/thread, vectorized
// ---------------------------------------------------------------------------
__global__ void k_hist(const int* __restrict__ indices, int n_edges) {
    int t = blockIdx.x * blockDim.x + threadIdx.x;
    int base = t * 8;
    if (base + 8 <= n_edges) {
        int4 a = __ldg(reinterpret_cast<const int4*>(indices) + t * 2);
        int4 b = __ldg(reinterpret_cast<const int4*>(indices) + t * 2 + 1);
        atomicAdd(&g_cnt[a.x], 1); atomicAdd(&g_cnt[a.y], 1);
        atomicAdd(&g_cnt[a.z], 1); atomicAdd(&g_cnt[a.w], 1);
        atomicAdd(&g_cnt[b.x], 1); atomicAdd(&g_cnt[b.y], 1);
        atomicAdd(&g_cnt[b.z], 1); atomicAdd(&g_cnt[b.w], 1);
    } else {
        for (int e = base; e < n_edges; e++)
            atomicAdd(&g_cnt[__ldg(indices + e)], 1);
    }
}

// ---------------------------------------------------------------------------
// 2) exclusive scan (single block)
// ---------------------------------------------------------------------------
__global__ void k_scan(int n) {
    __shared__ int part[1024];
    int tid = threadIdx.x;
    int chunk = (n + 1023) / 1024;
    int start = tid * chunk;
    int end   = min(start + chunk, n);
    int s = 0;
    for (int i = start; i < end; i++) s += g_cnt[i];
    part[tid] = s;
    __syncthreads();
    for (int off = 1; off < 1024; off <<= 1) {
        int v = 0;
        if (tid >= off) v = part[tid - off];
        __syncthreads();
        if (tid >= off) part[tid] += v;
        __syncthreads();
    }
    int run = (tid == 0) ? 0 : part[tid - 1];
    for (int i = start; i < end; i++) {
        g_rowptr[i] = run;
        g_rowpos[i] = run;
        run += g_cnt[i];
    }
    if (end == n && start <= n) g_rowptr[n] = run;
}

// ---------------------------------------------------------------------------
// 3) scatter — 8 edges/thread, single packed 4B write per edge
// ---------------------------------------------------------------------------
__global__ void k_scatter(const int* __restrict__ indices,
                          const int* __restrict__ ptype, int n_edges) {
    int t = blockIdx.x * blockDim.x + threadIdx.x;
    int base = t * 8;
    if (base + 8 <= n_edges) {
        int4 r0 = __ldg(reinterpret_cast<const int4*>(indices) + t * 2);
        int4 r1 = __ldg(reinterpret_cast<const int4*>(indices) + t * 2 + 1);
        int4 c0 = __ldg(reinterpret_cast<const int4*>(indices + n_edges) + t * 2);
        int4 c1 = __ldg(reinterpret_cast<const int4*>(indices + n_edges) + t * 2 + 1);
        int4 p0 = __ldg(reinterpret_cast<const int4*>(ptype) + t * 2);
        int4 p1 = __ldg(reinterpret_cast<const int4*>(ptype) + t * 2 + 1);
        int pos;
        pos = atomicAdd(&g_rowpos[r0.x], 1); g_col_s[pos] = c0.x | (p0.x << 24);
        pos = atomicAdd(&g_rowpos[r0.y], 1); g_col_s[pos] = c0.y | (p0.y << 24);
        pos = atomicAdd(&g_rowpos[r0.z], 1); g_col_s[pos] = c0.z | (p0.z << 24);
        pos = atomicAdd(&g_rowpos[r0.w], 1); g_col_s[pos] = c0.w | (p0.w << 24);
        pos = atomicAdd(&g_rowpos[r1.x], 1); g_col_s[pos] = c1.x | (p1.x << 24);
        pos = atomicAdd(&g_rowpos[r1.y], 1); g_col_s[pos] = c1.y | (p1.y << 24);
        pos = atomicAdd(&g_rowpos[r1.z], 1); g_col_s[pos] = c1.z | (p1.z << 24);
        pos = atomicAdd(&g_rowpos[r1.w], 1); g_col_s[pos] = c1.w | (p1.w << 24);
    } else {
        for (int e = base; e < n_edges; e++) {
            int row = __ldg(indices + e);
            int col = __ldg(indices + n_edges + e);
            int pt  = __ldg(ptype + e);
            int pos = atomicAdd(&g_rowpos[row], 1);
            g_col_s[pos] = col | (pt << 24);
        }
    }
}

// ---------------------------------------------------------------------------
// 4) fused: warp per row, half-warp per edge, ONE sweep, 2 edges/iter.
//    Lean registers (<=51 via launch_bounds) for 5 blocks/SM occupancy.
// ---------------------------------------------------------------------------
__device__ __forceinline__ float dot8h(float4 qa, float4 qb, uint4 kr) {
    float2 k0 = __half22float2(*reinterpret_cast<__half2*>(&kr.x));
    float2 k1 = __half22float2(*reinterpret_cast<__half2*>(&kr.y));
    float2 k2 = __half22float2(*reinterpret_cast<__half2*>(&kr.z));
    float2 k3 = __half22float2(*reinterpret_cast<__half2*>(&kr.w));
    return qa.x * k0.x + qa.y * k0.y + qa.z * k1.x + qa.w * k1.y
         + qb.x * k2.x + qb.y * k2.y + qb.z * k3.x + qb.w * k3.y;
}

__global__ void __launch_bounds__(256, 5)
k_fused(const float* __restrict__ q, float* __restrict__ out, int n_nodes) {
    __shared__ float s_pexp[PTYPES];
    if (threadIdx.x < PTYPES) s_pexp[threadIdx.x] = g_pexp[threadIdx.x];
    __syncthreads();

    int warp = (blockIdx.x * blockDim.x + threadIdx.x) >> 5;
    int lane = threadIdx.x & 31;
    if (warp >= n_nodes) return;
    const int row  = warp;
    const int half = lane >> 4;   // which edge of the pair
    const int hl   = lane & 15;   // component group 8hl..8hl+7
    const int beg = g_rowptr[row];
    const int end = g_rowptr[row + 1];

    float acc0[8] = {0,0,0,0,0,0,0,0};
    float acc1[8] = {0,0,0,0,0,0,0,0};
    float d0 = 0.f, d1 = 0.f;
    float res[8];

    if (beg < end) {
        const float inv_sqrt_h = 0.08838834764831845f;  // 1/sqrt(128)
        const float* qrow = q + (size_t)row * HDIM + hl * 8;
        float4 qa = __ldg(reinterpret_cast<const float4*>(qrow));
        float4 qb = __ldg(reinterpret_cast<const float4*>(qrow) + 1);
        qa.x *= inv_sqrt_h; qa.y *= inv_sqrt_h; qa.z *= inv_sqrt_h; qa.w *= inv_sqrt_h;
        qb.x *= inv_sqrt_h; qb.y *= inv_sqrt_h; qb.z *= inv_sqrt_h; qb.w *= inv_sqrt_h;
        float er = g_expl * __half2float(__ldg(g_eh + (size_t)row * EDIM + hl));

        // uniform loop: 2 edges per iteration (one per half), predicated
        for (int j = beg; j < end; j += 2) {
            int  jj    = j + half;
            bool valid = jj < end;
            int  pk    = __ldg(g_col_s + (valid ? jj : beg));
            int  c     = pk & 0xFFFFFF;
            uint4 kr = __ldg(reinterpret_cast<const uint4*>(g_kh + (size_t)c * HDIM + hl * 8));
            uint4 vr = __ldg(reinterpret_cast<const uint4*>(g_vh + (size_t)c * HDIM + hl * 8));
            float ec = __half2float(__ldg(g_eh + (size_t)c * EDIM + hl));

            float z = dot8h(qa, qb, kr) + er * ec;
            #pragma unroll
            for (int o = 8; o > 0; o >>= 1)
                z += __shfl_xor_sync(0xffffffffu, z, o);

            float e0 = valid ? __expf(z) : 0.f;
            float pw = valid ? s_pexp[((unsigned)pk) >> 24] : 0.f;
            d0 += e0;
            d1 += pw;

            float2 v0 = __half22float2(*reinterpret_cast<__half2*>(&vr.x));
            float2 v1 = __half22float2(*reinterpret_cast<__half2*>(&vr.y));
            float2 v2 = __half22float2(*reinterpret_cast<__half2*>(&vr.z));
            float2 v3 = __half22float2(*reinterpret_cast<__half2*>(&vr.w));
            acc0[0] += e0 * v0.x; acc0[1] += e0 * v0.y;
            acc0[2] += e0 * v1.x; acc0[3] += e0 * v1.y;
            acc0[4] += e0 * v2.x; acc0[5] += e0 * v2.y;
            acc0[6] += e0 * v3.x; acc0[7] += e0 * v3.y;
            acc1[0] += pw * v0.x; acc1[1] += pw * v0.y;
            acc1[2] += pw * v1.x; acc1[3] += pw * v1.y;
            acc1[4] += pw * v2.x; acc1[5] += pw * v2.y;
            acc1[6] += pw * v3.x; acc1[7] += pw * v3.y;
        }

        // combine halves and normalize
        d0 += __shfl_xor_sync(0xffffffffu, d0, 16);
        d1 += __shfl_xor_sync(0xffffffffu, d1, 16);
        float i0 = 0.5f / d0;
        float i1 = 0.5f / d1;
        #pragma unroll
        for (int i = 0; i < 8; i++) {
            acc0[i] += __shfl_xor_sync(0xffffffffu, acc0[i], 16);
            acc1[i] += __shfl_xor_sync(0xffffffffu, acc1[i], 16);
            res[i] = i0 * acc0[i] + i1 * acc1[i];
        }
    } else {
        #pragma unroll
        for (int i = 0; i < 8; i++) res[i] = 0.f;
    }

    if (half == 0) {
        float4* o = reinterpret_cast<float4*>(out + (size_t)row * HDIM + hl * 8);
        o[0] = make_float4(res[0], res[1], res[2], res[3]);
        o[1] = make_float4(res[4], res[5], res[6], res[7]);
    }
}

// ---------------------------------------------------------------------------
extern "C" void kernel_launch(void* const* d_in, const int* in_sizes, int n_in,
                              void* d_out, int out_size) {
    const float* q       = (const float*)d_in[0];
    const float* k       = (const float*)d_in[1];
    const float* v       = (const float*)d_in[2];
    const float* eigs    = (const float*)d_in[3];
    const float* lambda0 = (const float*)d_in[4];
    const float* path_w  = (const float*)d_in[5];
    const int*   indices = (const int*)d_in[6];
    const int*   ptype   = (const int*)d_in[7];
    float*       out     = (float*)d_out;

    int n_edges = in_sizes[6] / 2;
    int n_nodes = in_sizes[0] / HDIM;
    if (n_edges > EDGES)  n_edges = EDGES;
    if (n_nodes > NNODES) n_nodes = NNODES;

    int eb8 = (n_edges / 8 + 255) / 256 + 1;
    int rb  = (n_nodes * 32 + 255) / 256;

    k_prep<<<2048, 256>>>(k, v, eigs, lambda0, path_w, n_nodes);
    k_hist<<<eb8, 256>>>(indices, n_edges);
    k_scan<<<1, 1024>>>(n_nodes);
    k_scatter<<<eb8, 256>>>(indices, ptype, n_edges);
    k_fused<<<rb, 256>>>(q, out, n_nodes);
}

// round 10
// speedup vs baseline: 1.0622x; 1.0622x over previous
#include <cuda_runtime.h>
#include <cuda_fp16.h>
#include <math.h>

#define NNODES 100000
#define EDGES  3200000
#define HDIM   128
#define EDIM   16
#define PTYPES 6

// ---- __device__ scratch (allocations are banned) ----
__device__ int    g_cnt[NNODES];
__device__ int    g_rowptr[NNODES + 1];
__device__ int    g_rowpos[NNODES];
__device__ int    g_col_s[EDGES];       // CSR-ordered packed (col | ptype<<24)
__device__ __half g_kh[NNODES * HDIM];  // fp16 k     (25.6 MB)
__device__ __half g_vh[NNODES * HDIM];  // fp16 v     (25.6 MB)
__device__ __half g_eh[NNODES * EDIM];  // fp16 eigs   (3.2 MB)
__device__ float  g_pexp[PTYPES];
__device__ float  g_expl;

// ---------------------------------------------------------------------------
// 0) prep: zero histogram, exp tables, fp16 copies of k, v, eigs  (R6 version)
// ---------------------------------------------------------------------------
__global__ void k_prep(const float* __restrict__ k,
                       const float* __restrict__ v,
                       const float* __restrict__ eigs,
                       const float* __restrict__ lambda0,
                       const float* __restrict__ path_w, int n_nodes) {
    int tid = blockIdx.x * blockDim.x + threadIdx.x;
    int stride = gridDim.x * blockDim.x;

    for (int i = tid; i < n_nodes; i += stride) g_cnt[i] = 0;

    int nk4 = n_nodes * (HDIM / 4);
    for (int i = tid; i < nk4; i += stride) {
        float4 f = __ldg(reinterpret_cast<const float4*>(k) + i);
        __half2 lo = __floats2half2_rn(f.x, f.y);
        __half2 hi = __floats2half2_rn(f.z, f.w);
        uint2 o;
        o.x = *reinterpret_cast<unsigned*>(&lo);
        o.y = *reinterpret_cast<unsigned*>(&hi);
        reinterpret_cast<uint2*>(g_kh)[i] = o;
    }
    for (int i = tid; i < nk4; i += stride) {
        float4 f = __ldg(reinterpret_cast<const float4*>(v) + i);
        __half2 lo = __floats2half2_rn(f.x, f.y);
        __half2 hi = __floats2half2_rn(f.z, f.w);
        uint2 o;
        o.x = *reinterpret_cast<unsigned*>(&lo);
        o.y = *reinterpret_cast<unsigned*>(&hi);
        reinterpret_cast<uint2*>(g_vh)[i] = o;
    }
    int ne4 = n_nodes * (EDIM / 4);
    for (int i = tid; i < ne4; i += stride) {
        float4 f = __ldg(reinterpret_cast<const float4*>(eigs) + i);
        __half2 lo = __floats2half2_rn(f.x, f.y);
        __half2 hi = __floats2half2_rn(f.z, f.w);
        uint2 o;
        o.x = *reinterpret_cast<unsigned*>(&lo);
        o.y = *reinterpret_cast<unsigned*>(&hi);
        reinterpret_cast<uint2*>(g_eh)[i] = o;
    }

    if (tid < PTYPES) g_pexp[tid] = expf(path_w[tid]);
    if (tid == 0)     g_expl = expf(lambda0[0]);
}

// ---------------------------------------------------------------------------
// 1) histogram of destination rows — 8 edges/thread, vectorized
// ---------------------------------------------------------------------------
__global__ void k_hist(const int* __restrict__ indices, int n_edges) {
    int t = blockIdx.x * blockDim.x + threadIdx.x;
    int base = t * 8;
    if (base + 8 <= n_edges) {
        int4 a = __ldg(reinterpret_cast<const int4*>(indices) + t * 2);
        int4 b = __ldg(reinterpret_cast<const int4*>(indices) + t * 2 + 1);
        atomicAdd(&g_cnt[a.x], 1); atomicAdd(&g_cnt[a.y], 1);
        atomicAdd(&g_cnt[a.z], 1); atomicAdd(&g_cnt[a.w], 1);
        atomicAdd(&g_cnt[b.x], 1); atomicAdd(&g_cnt[b.y], 1);
        atomicAdd(&g_cnt[b.z], 1); atomicAdd(&g_cnt[b.w], 1);
    } else {
        for (int e = base; e < n_edges; e++)
            atomicAdd(&g_cnt[__ldg(indices + e)], 1);
    }
}

// ---------------------------------------------------------------------------
// 2) exclusive scan (single block)
// ---------------------------------------------------------------------------
__global__ void k_scan(int n) {
    __shared__ int part[1024];
    int tid = threadIdx.x;
    int chunk = (n + 1023) / 1024;
    int start = tid * chunk;
    int end   = min(start + chunk, n);
    int s = 0;
    for (int i = start; i < end; i++) s += g_cnt[i];
    part[tid] = s;
    __syncthreads();
    for (int off = 1; off < 1024; off <<= 1) {
        int v = 0;
        if (tid >= off) v = part[tid - off];
        __syncthreads();
        if (tid >= off) part[tid] += v;
        __syncthreads();
    }
    int run = (tid == 0) ? 0 : part[tid - 1];
    for (int i = start; i < end; i++) {
        g_rowptr[i] = run;
        g_rowpos[i] = run;
        run += g_cnt[i];
    }
    if (end == n && start <= n) g_rowptr[n] = run;
}

// ---------------------------------------------------------------------------
// 3) scatter — 8 edges/thread, single packed 4B write per edge
// ---------------------------------------------------------------------------
__global__ void k_scatter(const int* __restrict__ indices,
                          const int* __restrict__ ptype, int n_edges) {
    int t = blockIdx.x * blockDim.x + threadIdx.x;
    int base = t * 8;
    if (base + 8 <= n_edges) {
        int4 r0 = __ldg(reinterpret_cast<const int4*>(indices) + t * 2);
        int4 r1 = __ldg(reinterpret_cast<const int4*>(indices) + t * 2 + 1);
        int4 c0 = __ldg(reinterpret_cast<const int4*>(indices + n_edges) + t * 2);
        int4 c1 = __ldg(reinterpret_cast<const int4*>(indices + n_edges) + t * 2 + 1);
        int4 p0 = __ldg(reinterpret_cast<const int4*>(ptype) + t * 2);
        int4 p1 = __ldg(reinterpret_cast<const int4*>(ptype) + t * 2 + 1);
        int pos;
        pos = atomicAdd(&g_rowpos[r0.x], 1); g_col_s[pos] = c0.x | (p0.x << 24);
        pos = atomicAdd(&g_rowpos[r0.y], 1); g_col_s[pos] = c0.y | (p0.y << 24);
        pos = atomicAdd(&g_rowpos[r0.z], 1); g_col_s[pos] = c0.z | (p0.z << 24);
        pos = atomicAdd(&g_rowpos[r0.w], 1); g_col_s[pos] = c0.w | (p0.w << 24);
        pos = atomicAdd(&g_rowpos[r1.x], 1); g_col_s[pos] = c1.x | (p1.x << 24);
        pos = atomicAdd(&g_rowpos[r1.y], 1); g_col_s[pos] = c1.y | (p1.y << 24);
        pos = atomicAdd(&g_rowpos[r1.z], 1); g_col_s[pos] = c1.z | (p1.z << 24);
        pos = atomicAdd(&g_rowpos[r1.w], 1); g_col_s[pos] = c1.w | (p1.w << 24);
    } else {
        for (int e = base; e < n_edges; e++) {
            int row = __ldg(indices + e);
            int col = __ldg(indices + n_edges + e);
            int pt  = __ldg(ptype + e);
            int pos = atomicAdd(&g_rowpos[row], 1);
            g_col_s[pos] = col | (pt << 24);
        }
    }
}

// ---------------------------------------------------------------------------
// 4) fused (R7 version, measured 240us): warp per row, half-warp per edge,
//    one sweep, 4 edges per iteration, predicated 2-edge tail.
// ---------------------------------------------------------------------------
__device__ __forceinline__ float dot8h(float4 qa, float4 qb, uint4 kr) {
    float2 k0 = __half22float2(*reinterpret_cast<__half2*>(&kr.x));
    float2 k1 = __half22float2(*reinterpret_cast<__half2*>(&kr.y));
    float2 k2 = __half22float2(*reinterpret_cast<__half2*>(&kr.z));
    float2 k3 = __half22float2(*reinterpret_cast<__half2*>(&kr.w));
    return qa.x * k0.x + qa.y * k0.y + qa.z * k1.x + qa.w * k1.y
         + qb.x * k2.x + qb.y * k2.y + qb.z * k3.x + qb.w * k3.y;
}

__global__ void __launch_bounds__(256)
k_fused(const float* __restrict__ q, float* __restrict__ out, int n_nodes) {
    __shared__ float s_pexp[PTYPES];
    if (threadIdx.x < PTYPES) s_pexp[threadIdx.x] = g_pexp[threadIdx.x];
    __syncthreads();

    int warp = (blockIdx.x * blockDim.x + threadIdx.x) >> 5;
    int lane = threadIdx.x & 31;
    if (warp >= n_nodes) return;
    const int row  = warp;
    const int half = lane >> 4;   // which edge of the pair
    const int hl   = lane & 15;   // lane within half: components 8hl..8hl+7
    const int beg = g_rowptr[row];
    const int end = g_rowptr[row + 1];

    float acc0[8] = {0,0,0,0,0,0,0,0};
    float acc1[8] = {0,0,0,0,0,0,0,0};
    float d0 = 0.f, d1 = 0.f;
    float res[8];

    if (beg < end) {
        const float inv_sqrt_h = 0.08838834764831845f;  // 1/sqrt(128)
        const float* qrow = q + (size_t)row * HDIM + hl * 8;
        float4 qa = __ldg(reinterpret_cast<const float4*>(qrow));
        float4 qb = __ldg(reinterpret_cast<const float4*>(qrow) + 1);
        qa.x *= inv_sqrt_h; qa.y *= inv_sqrt_h; qa.z *= inv_sqrt_h; qa.w *= inv_sqrt_h;
        qb.x *= inv_sqrt_h; qb.y *= inv_sqrt_h; qb.z *= inv_sqrt_h; qb.w *= inv_sqrt_h;
        float er = g_expl * __half2float(__ldg(g_eh + (size_t)row * EDIM + hl));

        int j = beg;
        // main loop: 4 edges per iteration (2 per half), all valid
        for (; j + 4 <= end; j += 4) {
            int j0 = j + half;
            int j1 = j + 2 + half;
            int pk0 = __ldg(g_col_s + j0);
            int pk1 = __ldg(g_col_s + j1);
            int c0 = pk0 & 0xFFFFFF, c1 = pk1 & 0xFFFFFF;
            uint4 kr0 = __ldg(reinterpret_cast<const uint4*>(g_kh + (size_t)c0 * HDIM + hl * 8));
            uint4 kr1 = __ldg(reinterpret_cast<const uint4*>(g_kh + (size_t)c1 * HDIM + hl * 8));
            uint4 vr0 = __ldg(reinterpret_cast<const uint4*>(g_vh + (size_t)c0 * HDIM + hl * 8));
            uint4 vr1 = __ldg(reinterpret_cast<const uint4*>(g_vh + (size_t)c1 * HDIM + hl * 8));
            float ec0 = __half2float(__ldg(g_eh + (size_t)c0 * EDIM + hl));
            float ec1 = __half2float(__ldg(g_eh + (size_t)c1 * EDIM + hl));

            float z0 = dot8h(qa, qb, kr0) + er * ec0;
            float z1 = dot8h(qa, qb, kr1) + er * ec1;
            #pragma unroll
            for (int o = 8; o > 0; o >>= 1) {
                z0 += __shfl_xor_sync(0xffffffffu, z0, o);
                z1 += __shfl_xor_sync(0xffffffffu, z1, o);
            }
            float e00 = __expf(z0);
            float e01 = __expf(z1);
            float pw0 = s_pexp[((unsigned)pk0) >> 24];
            float pw1 = s_pexp[((unsigned)pk1) >> 24];
            d0 += e00 + e01;
            d1 += pw0 + pw1;

            float2 v0[4], v1[4];
            v0[0] = __half22float2(*reinterpret_cast<__half2*>(&vr0.x));
            v0[1] = __half22float2(*reinterpret_cast<__half2*>(&vr0.y));
            v0[2] = __half22float2(*reinterpret_cast<__half2*>(&vr0.z));
            v0[3] = __half22float2(*reinterpret_cast<__half2*>(&vr0.w));
            v1[0] = __half22float2(*reinterpret_cast<__half2*>(&vr1.x));
            v1[1] = __half22float2(*reinterpret_cast<__half2*>(&vr1.y));
            v1[2] = __half22float2(*reinterpret_cast<__half2*>(&vr1.z));
            v1[3] = __half22float2(*reinterpret_cast<__half2*>(&vr1.w));
            #pragma unroll
            for (int i = 0; i < 4; i++) {
                acc0[2*i]   += e00 * v0[i].x + e01 * v1[i].x;
                acc0[2*i+1] += e00 * v0[i].y + e01 * v1[i].y;
                acc1[2*i]   += pw0 * v0[i].x + pw1 * v1[i].x;
                acc1[2*i+1] += pw0 * v0[i].y + pw1 * v1[i].y;
            }
        }
        // tail: up to 3 edges, 2 per step with per-half predication
        for (; j < end; j += 2) {
            int jj = j + half;
            bool valid = jj < end;
            int pk0 = __ldg(g_col_s + (valid ? jj : beg));
            int c0 = pk0 & 0xFFFFFF;
            uint4 kr0 = __ldg(reinterpret_cast<const uint4*>(g_kh + (size_t)c0 * HDIM + hl * 8));
            uint4 vr0 = __ldg(reinterpret_cast<const uint4*>(g_vh + (size_t)c0 * HDIM + hl * 8));
            float ec0 = __half2float(__ldg(g_eh + (size_t)c0 * EDIM + hl));
            float z0 = dot8h(qa, qb, kr0) + er * ec0;
            #pragma unroll
            for (int o = 8; o > 0; o >>= 1)
                z0 += __shfl_xor_sync(0xffffffffu, z0, o);
            float e00 = valid ? __expf(z0) : 0.f;
            float pw0 = valid ? s_pexp[((unsigned)pk0) >> 24] : 0.f;
            d0 += e00;
            d1 += pw0;
            float2 v0[4];
            v0[0] = __half22float2(*reinterpret_cast<__half2*>(&vr0.x));
            v0[1] = __half22float2(*reinterpret_cast<__half2*>(&vr0.y));
            v0[2] = __half22float2(*reinterpret_cast<__half2*>(&vr0.z));
            v0[3] = __half22float2(*reinterpret_cast<__half2*>(&vr0.w));
            #pragma unroll
            for (int i = 0; i < 4; i++) {
                acc0[2*i]   += e00 * v0[i].x;
                acc0[2*i+1] += e00 * v0[i].y;
                acc1[2*i]   += pw0 * v0[i].x;
                acc1[2*i+1] += pw0 * v0[i].y;
            }
        }

        // combine halves
        d0 += __shfl_xor_sync(0xffffffffu, d0, 16);
        d1 += __shfl_xor_sync(0xffffffffu, d1, 16);
        float i0 = 0.5f / d0;
        float i1 = 0.5f / d1;
        #pragma unroll
        for (int i = 0; i < 8; i++) {
            acc0[i] += __shfl_xor_sync(0xffffffffu, acc0[i], 16);
            acc1[i] += __shfl_xor_sync(0xffffffffu, acc1[i], 16);
            res[i] = i0 * acc0[i] + i1 * acc1[i];
        }
    } else {
        #pragma unroll
        for (int i = 0; i < 8; i++) res[i] = 0.f;
    }

    if (half == 0) {
        float4* o = reinterpret_cast<float4*>(out + (size_t)row * HDIM + hl * 8);
        o[0] = make_float4(res[0], res[1], res[2], res[3]);
        o[1] = make_float4(res[4], res[5], res[6], res[7]);
    }
}

// ---------------------------------------------------------------------------
extern "C" void kernel_launch(void* const* d_in, const int* in_sizes, int n_in,
                              void* d_out, int out_size) {
    const float* q       = (const float*)d_in[0];
    const float* k       = (const float*)d_in[1];
    const float* v       = (const float*)d_in[2];
    const float* eigs    = (const float*)d_in[3];
    const float* lambda0 = (const float*)d_in[4];
    const float* path_w  = (const float*)d_in[5];
    const int*   indices = (const int*)d_in[6];
    const int*   ptype   = (const int*)d_in[7];
    float*       out     = (float*)d_out;

    int n_edges = in_sizes[6] / 2;
    int n_nodes = in_sizes[0] / HDIM;
    if (n_edges > EDGES)  n_edges = EDGES;
    if (n_nodes > NNODES) n_nodes = NNODES;

    int eb8 = (n_edges / 8 + 255) / 256 + 1;
    int rb  = (n_nodes * 32 + 255) / 256;

    k_prep<<<2048, 256>>>(k, v, eigs, lambda0, path_w, n_nodes);
    k_hist<<<eb8, 256>>>(indices, n_edges);
    k_scan<<<1, 1024>>>(n_nodes);
    k_scatter<<<eb8, 256>>>(indices, ptype, n_edges);
    k_fused<<<rb, 256>>>(q, out, n_nodes);
}

// round 11
// speedup vs baseline: 1.6968x; 1.5974x over previous
#include <cuda_runtime.h>
#include <cuda_fp16.h>
#include <math.h>

#define NNODES 100000
#define EDGES  3200000
#define HDIM   128
#define EDIM   16
#define PTYPES 6
#define CAP    96     // bucket slots per row; Poisson(32) max-degree ~65

// ---- __device__ scratch (allocations are banned) ----
__device__ int    g_cnt[NNODES];          // per-row cursor (prep zeroes each replay)
__device__ int    g_bkt[NNODES * CAP];    // packed (col | ptype<<24), 38.4 MB
__device__ int    g_ovf;                  // spill count
__device__ int    g_sp_row[EDGES];        // spill rows (adversarial inputs only)
__device__ int    g_sp_pk[EDGES];         // spill packed entries
__device__ __half g_kh[NNODES * HDIM];    // fp16 k     (25.6 MB)
__device__ __half g_vh[NNODES * HDIM];    // fp16 v     (25.6 MB)
__device__ __half g_eh[NNODES * EDIM];    // fp16 eigs   (3.2 MB)
__device__ float  g_pexp[PTYPES];
__device__ float  g_expl;

// ---------------------------------------------------------------------------
// 0) prep: zero cursors + spill counter, exp tables, fp16 copies of k, v, eigs
// ---------------------------------------------------------------------------
__global__ void k_prep(const float* __restrict__ k,
                       const float* __restrict__ v,
                       const float* __restrict__ eigs,
                       const float* __restrict__ lambda0,
                       const float* __restrict__ path_w, int n_nodes) {
    int tid = blockIdx.x * blockDim.x + threadIdx.x;
    int stride = gridDim.x * blockDim.x;

    for (int i = tid; i < n_nodes; i += stride) g_cnt[i] = 0;

    int nk4 = n_nodes * (HDIM / 4);
    for (int i = tid; i < nk4; i += stride) {
        float4 f = __ldg(reinterpret_cast<const float4*>(k) + i);
        __half2 lo = __floats2half2_rn(f.x, f.y);
        __half2 hi = __floats2half2_rn(f.z, f.w);
        uint2 o;
        o.x = *reinterpret_cast<unsigned*>(&lo);
        o.y = *reinterpret_cast<unsigned*>(&hi);
        reinterpret_cast<uint2*>(g_kh)[i] = o;
    }
    for (int i = tid; i < nk4; i += stride) {
        float4 f = __ldg(reinterpret_cast<const float4*>(v) + i);
        __half2 lo = __floats2half2_rn(f.x, f.y);
        __half2 hi = __floats2half2_rn(f.z, f.w);
        uint2 o;
        o.x = *reinterpret_cast<unsigned*>(&lo);
        o.y = *reinterpret_cast<unsigned*>(&hi);
        reinterpret_cast<uint2*>(g_vh)[i] = o;
    }
    int ne4 = n_nodes * (EDIM / 4);
    for (int i = tid; i < ne4; i += stride) {
        float4 f = __ldg(reinterpret_cast<const float4*>(eigs) + i);
        __half2 lo = __floats2half2_rn(f.x, f.y);
        __half2 hi = __floats2half2_rn(f.z, f.w);
        uint2 o;
        o.x = *reinterpret_cast<unsigned*>(&lo);
        o.y = *reinterpret_cast<unsigned*>(&hi);
        reinterpret_cast<uint2*>(g_eh)[i] = o;
    }

    if (tid < PTYPES) g_pexp[tid] = expf(path_w[tid]);
    if (tid == 0) { g_expl = expf(lambda0[0]); g_ovf = 0; }
}

// ---------------------------------------------------------------------------
// 1) scatter — bucket append, 8 edges/thread, single packed 4B write/edge.
//    No histogram, no scan: rowptr is implicit (row * CAP).
// ---------------------------------------------------------------------------
__device__ __forceinline__ void bkt_put(int row, int pk) {
    int pos = atomicAdd(&g_cnt[row], 1);
    if (pos < CAP) {
        g_bkt[row * CAP + pos] = pk;
    } else {                          // adversarial-degree spill (never for bench input)
        int s = atomicAdd(&g_ovf, 1);
        g_sp_row[s] = row;
        g_sp_pk[s]  = pk;
    }
}

__global__ void k_scatter(const int* __restrict__ indices,
                          const int* __restrict__ ptype, int n_edges) {
    int t = blockIdx.x * blockDim.x + threadIdx.x;
    int base = t * 8;
    if (base + 8 <= n_edges) {
        int4 r0 = __ldg(reinterpret_cast<const int4*>(indices) + t * 2);
        int4 r1 = __ldg(reinterpret_cast<const int4*>(indices) + t * 2 + 1);
        int4 c0 = __ldg(reinterpret_cast<const int4*>(indices + n_edges) + t * 2);
        int4 c1 = __ldg(reinterpret_cast<const int4*>(indices + n_edges) + t * 2 + 1);
        int4 p0 = __ldg(reinterpret_cast<const int4*>(ptype) + t * 2);
        int4 p1 = __ldg(reinterpret_cast<const int4*>(ptype) + t * 2 + 1);
        bkt_put(r0.x, c0.x | (p0.x << 24));
        bkt_put(r0.y, c0.y | (p0.y << 24));
        bkt_put(r0.z, c0.z | (p0.z << 24));
        bkt_put(r0.w, c0.w | (p0.w << 24));
        bkt_put(r1.x, c1.x | (p1.x << 24));
        bkt_put(r1.y, c1.y | (p1.y << 24));
        bkt_put(r1.z, c1.z | (p1.z << 24));
        bkt_put(r1.w, c1.w | (p1.w << 24));
    } else {
        for (int e = base; e < n_edges; e++) {
            int row = __ldg(indices + e);
            int col = __ldg(indices + n_edges + e);
            int pt  = __ldg(ptype + e);
            bkt_put(row, col | (pt << 24));
        }
    }
}

// ---------------------------------------------------------------------------
// 2) fused (R7 loop, measured 240us): warp per row, half-warp per edge,
//    one sweep, 4 edges/iter, predicated 2-edge tail; bucket-indexed.
// ---------------------------------------------------------------------------
__device__ __forceinline__ float dot8h(float4 qa, float4 qb, uint4 kr) {
    float2 k0 = __half22float2(*reinterpret_cast<__half2*>(&kr.x));
    float2 k1 = __half22float2(*reinterpret_cast<__half2*>(&kr.y));
    float2 k2 = __half22float2(*reinterpret_cast<__half2*>(&kr.z));
    float2 k3 = __half22float2(*reinterpret_cast<__half2*>(&kr.w));
    return qa.x * k0.x + qa.y * k0.y + qa.z * k1.x + qa.w * k1.y
         + qb.x * k2.x + qb.y * k2.y + qb.z * k3.x + qb.w * k3.y;
}

__global__ void __launch_bounds__(256)
k_fused(const float* __restrict__ q, float* __restrict__ out, int n_nodes) {
    __shared__ float s_pexp[PTYPES];
    if (threadIdx.x < PTYPES) s_pexp[threadIdx.x] = g_pexp[threadIdx.x];
    __syncthreads();

    int warp = (blockIdx.x * blockDim.x + threadIdx.x) >> 5;
    int lane = threadIdx.x & 31;
    if (warp >= n_nodes) return;
    const int row  = warp;
    const int half = lane >> 4;
    const int hl   = lane & 15;
    const int cnt  = g_cnt[row];
    const int deg  = cnt < CAP ? cnt : CAP;
    const int beg  = row * CAP;
    const int end  = beg + deg;
    const int ovf  = g_ovf;          // 0 for the bench input

    float acc0[8] = {0,0,0,0,0,0,0,0};
    float acc1[8] = {0,0,0,0,0,0,0,0};
    float d0 = 0.f, d1 = 0.f;
    float res[8];

    if (deg > 0 || ovf > 0) {
        const float inv_sqrt_h = 0.08838834764831845f;  // 1/sqrt(128)
        const float* qrow = q + (size_t)row * HDIM + hl * 8;
        float4 qa = __ldg(reinterpret_cast<const float4*>(qrow));
        float4 qb = __ldg(reinterpret_cast<const float4*>(qrow) + 1);
        qa.x *= inv_sqrt_h; qa.y *= inv_sqrt_h; qa.z *= inv_sqrt_h; qa.w *= inv_sqrt_h;
        qb.x *= inv_sqrt_h; qb.y *= inv_sqrt_h; qb.z *= inv_sqrt_h; qb.w *= inv_sqrt_h;
        float er = g_expl * __half2float(__ldg(g_eh + (size_t)row * EDIM + hl));

        int j = beg;
        for (; j + 4 <= end; j += 4) {
            int j0 = j + half;
            int j1 = j + 2 + half;
            int pk0 = __ldg(g_bkt + j0);
            int pk1 = __ldg(g_bkt + j1);
            int c0 = pk0 & 0xFFFFFF, c1 = pk1 & 0xFFFFFF;
            uint4 kr0 = __ldg(reinterpret_cast<const uint4*>(g_kh + (size_t)c0 * HDIM + hl * 8));
            uint4 kr1 = __ldg(reinterpret_cast<const uint4*>(g_kh + (size_t)c1 * HDIM + hl * 8));
            uint4 vr0 = __ldg(reinterpret_cast<const uint4*>(g_vh + (size_t)c0 * HDIM + hl * 8));
            uint4 vr1 = __ldg(reinterpret_cast<const uint4*>(g_vh + (size_t)c1 * HDIM + hl * 8));
            float ec0 = __half2float(__ldg(g_eh + (size_t)c0 * EDIM + hl));
            float ec1 = __half2float(__ldg(g_eh + (size_t)c1 * EDIM + hl));

            float z0 = dot8h(qa, qb, kr0) + er * ec0;
            float z1 = dot8h(qa, qb, kr1) + er * ec1;
            #pragma unroll
            for (int o = 8; o > 0; o >>= 1) {
                z0 += __shfl_xor_sync(0xffffffffu, z0, o);
                z1 += __shfl_xor_sync(0xffffffffu, z1, o);
            }
            float e00 = __expf(z0);
            float e01 = __expf(z1);
            float pw0 = s_pexp[((unsigned)pk0) >> 24];
            float pw1 = s_pexp[((unsigned)pk1) >> 24];
            d0 += e00 + e01;
            d1 += pw0 + pw1;

            float2 v0[4], v1[4];
            v0[0] = __half22float2(*reinterpret_cast<__half2*>(&vr0.x));
            v0[1] = __half22float2(*reinterpret_cast<__half2*>(&vr0.y));
            v0[2] = __half22float2(*reinterpret_cast<__half2*>(&vr0.z));
            v0[3] = __half22float2(*reinterpret_cast<__half2*>(&vr0.w));
            v1[0] = __half22float2(*reinterpret_cast<__half2*>(&vr1.x));
            v1[1] = __half22float2(*reinterpret_cast<__half2*>(&vr1.y));
            v1[2] = __half22float2(*reinterpret_cast<__half2*>(&vr1.z));
            v1[3] = __half22float2(*reinterpret_cast<__half2*>(&vr1.w));
            #pragma unroll
            for (int i = 0; i < 4; i++) {
                acc0[2*i]   += e00 * v0[i].x + e01 * v1[i].x;
                acc0[2*i+1] += e00 * v0[i].y + e01 * v1[i].y;
                acc1[2*i]   += pw0 * v0[i].x + pw1 * v1[i].x;
                acc1[2*i+1] += pw0 * v0[i].y + pw1 * v1[i].y;
            }
        }
        for (; j < end; j += 2) {
            int jj = j + half;
            bool valid = jj < end;
            int pk0 = __ldg(g_bkt + (valid ? jj : beg));
            int c0 = pk0 & 0xFFFFFF;
            uint4 kr0 = __ldg(reinterpret_cast<const uint4*>(g_kh + (size_t)c0 * HDIM + hl * 8));
            uint4 vr0 = __ldg(reinterpret_cast<const uint4*>(g_vh + (size_t)c0 * HDIM + hl * 8));
            float ec0 = __half2float(__ldg(g_eh + (size_t)c0 * EDIM + hl));
            float z0 = dot8h(qa, qb, kr0) + er * ec0;
            #pragma unroll
            for (int o = 8; o > 0; o >>= 1)
                z0 += __shfl_xor_sync(0xffffffffu, z0, o);
            float e00 = valid ? __expf(z0) : 0.f;
            float pw0 = valid ? s_pexp[((unsigned)pk0) >> 24] : 0.f;
            d0 += e00;
            d1 += pw0;
            float2 v0[4];
            v0[0] = __half22float2(*reinterpret_cast<__half2*>(&vr0.x));
            v0[1] = __half22float2(*reinterpret_cast<__half2*>(&vr0.y));
            v0[2] = __half22float2(*reinterpret_cast<__half2*>(&vr0.z));
            v0[3] = __half22float2(*reinterpret_cast<__half2*>(&vr0.w));
            #pragma unroll
            for (int i = 0; i < 4; i++) {
                acc0[2*i]   += e00 * v0[i].x;
                acc0[2*i+1] += e00 * v0[i].y;
                acc1[2*i]   += pw0 * v0[i].x;
                acc1[2*i+1] += pw0 * v0[i].y;
            }
        }

        // spill entries (only when some row exceeded CAP; never for bench input)
        for (int s = 0; s < ovf; s++) {
            if (g_sp_row[s] != row) continue;
            int pk0 = g_sp_pk[s];
            int c0 = pk0 & 0xFFFFFF;
            uint4 kr0 = __ldg(reinterpret_cast<const uint4*>(g_kh + (size_t)c0 * HDIM + hl * 8));
            uint4 vr0 = __ldg(reinterpret_cast<const uint4*>(g_vh + (size_t)c0 * HDIM + hl * 8));
            float ec0 = __half2float(__ldg(g_eh + (size_t)c0 * EDIM + hl));
            float z0 = dot8h(qa, qb, kr0) + er * ec0;
            #pragma unroll
            for (int o = 8; o > 0; o >>= 1)
                z0 += __shfl_xor_sync(0xffffffffu, z0, o);
            bool act = (half == 0);      // count each spill edge once
            float e00 = act ? __expf(z0) : 0.f;
            float pw0 = act ? s_pexp[((unsigned)pk0) >> 24] : 0.f;
            d0 += e00;
            d1 += pw0;
            float2 v0[4];
            v0[0] = __half22float2(*reinterpret_cast<__half2*>(&vr0.x));
            v0[1] = __half22float2(*reinterpret_cast<__half2*>(&vr0.y));
            v0[2] = __half22float2(*reinterpret_cast<__half2*>(&vr0.z));
            v0[3] = __half22float2(*reinterpret_cast<__half2*>(&vr0.w));
            #pragma unroll
            for (int i = 0; i < 4; i++) {
                acc0[2*i]   += e00 * v0[i].x;
                acc0[2*i+1] += e00 * v0[i].y;
                acc1[2*i]   += pw0 * v0[i].x;
                acc1[2*i+1] += pw0 * v0[i].y;
            }
        }

        // combine halves and normalize
        d0 += __shfl_xor_sync(0xffffffffu, d0, 16);
        d1 += __shfl_xor_sync(0xffffffffu, d1, 16);
        float i0 = (d0 != 0.f) ? 0.5f / d0 : 0.f;
        float i1 = (d1 != 0.f) ? 0.5f / d1 : 0.f;
        #pragma unroll
        for (int i = 0; i < 8; i++) {
            acc0[i] += __shfl_xor_sync(0xffffffffu, acc0[i], 16);
            acc1[i] += __shfl_xor_sync(0xffffffffu, acc1[i], 16);
            res[i] = i0 * acc0[i] + i1 * acc1[i];
        }
    } else {
        #pragma unroll
        for (int i = 0; i < 8; i++) res[i] = 0.f;
    }

    if (half == 0) {
        float4* o = reinterpret_cast<float4*>(out + (size_t)row * HDIM + hl * 8);
        o[0] = make_float4(res[0], res[1], res[2], res[3]);
        o[1] = make_float4(res[4], res[5], res[6], res[7]);
    }
}

// ---------------------------------------------------------------------------
extern "C" void kernel_launch(void* const* d_in, const int* in_sizes, int n_in,
                              void* d_out, int out_size) {
    const float* q       = (const float*)d_in[0];
    const float* k       = (const float*)d_in[1];
    const float* v       = (const float*)d_in[2];
    const float* eigs    = (const float*)d_in[3];
    const float* lambda0 = (const float*)d_in[4];
    const float* path_w  = (const float*)d_in[5];
    const int*   indices = (const int*)d_in[6];
    const int*   ptype   = (const int*)d_in[7];
    float*       out     = (float*)d_out;

    int n_edges = in_sizes[6] / 2;
    int n_nodes = in_sizes[0] / HDIM;
    if (n_edges > EDGES)  n_edges = EDGES;
    if (n_nodes > NNODES) n_nodes = NNODES;

    int eb8 = (n_edges / 8 + 255) / 256 + 1;
    int rb  = (n_nodes * 32 + 255) / 256;

    k_prep<<<2048, 256>>>(k, v, eigs, lambda0, path_w, n_nodes);
    k_scatter<<<eb8, 256>>>(indices, ptype, n_edges);
    k_fused<<<rb, 256>>>(q, out, n_nodes);
}

// round 12
// speedup vs baseline: 1.7541x; 1.0338x over previous
#include <cuda_runtime.h>
#include <cuda_fp16.h>
#include <math.h>

#define NNODES 100000
#define EDGES  3200000
#define HDIM   128
#define EDIM   16
#define PTYPES 6
#define CAP    96     // bucket slots per row; Poisson(32) max-degree ~65

// ---- __device__ scratch (allocations are banned) ----
__device__ int    g_cnt[NNODES];          // per-row cursor (prep zeroes each replay)
__device__ int    g_bkt[NNODES * CAP];    // packed (col | ptype<<24), 38.4 MB
__device__ int    g_ovf;                  // spill count
__device__ int    g_sp_row[EDGES];        // spill rows (adversarial inputs only)
__device__ int    g_sp_pk[EDGES];         // spill packed entries
__device__ __half g_kh[NNODES * HDIM];    // fp16 k     (25.6 MB)  -- keep in L2
__device__ __half g_vh[NNODES * HDIM];    // fp16 v     (25.6 MB)  -- keep in L2
__device__ __half g_eh[NNODES * EDIM];    // fp16 eigs   (3.2 MB)  -- keep in L2
__device__ float  g_pexp[PTYPES];
__device__ float  g_expl;

// ---------------------------------------------------------------------------
// 0) prep: zero cursors + spill counter, exp tables, fp16 copies of k, v, eigs
//    Streaming reads use __ldcs to avoid polluting L2.
// ---------------------------------------------------------------------------
__global__ void k_prep(const float* __restrict__ k,
                       const float* __restrict__ v,
                       const float* __restrict__ eigs,
                       const float* __restrict__ lambda0,
                       const float* __restrict__ path_w, int n_nodes) {
    int tid = blockIdx.x * blockDim.x + threadIdx.x;
    int stride = gridDim.x * blockDim.x;

    for (int i = tid; i < n_nodes; i += stride) g_cnt[i] = 0;

    int nk4 = n_nodes * (HDIM / 4);
    for (int i = tid; i < nk4; i += stride) {
        float4 f = __ldcs(reinterpret_cast<const float4*>(k) + i);
        __half2 lo = __floats2half2_rn(f.x, f.y);
        __half2 hi = __floats2half2_rn(f.z, f.w);
        uint2 o;
        o.x = *reinterpret_cast<unsigned*>(&lo);
        o.y = *reinterpret_cast<unsigned*>(&hi);
        reinterpret_cast<uint2*>(g_kh)[i] = o;
    }
    for (int i = tid; i < nk4; i += stride) {
        float4 f = __ldcs(reinterpret_cast<const float4*>(v) + i);
        __half2 lo = __floats2half2_rn(f.x, f.y);
        __half2 hi = __floats2half2_rn(f.z, f.w);
        uint2 o;
        o.x = *reinterpret_cast<unsigned*>(&lo);
        o.y = *reinterpret_cast<unsigned*>(&hi);
        reinterpret_cast<uint2*>(g_vh)[i] = o;
    }
    int ne4 = n_nodes * (EDIM / 4);
    for (int i = tid; i < ne4; i += stride) {
        float4 f = __ldcs(reinterpret_cast<const float4*>(eigs) + i);
        __half2 lo = __floats2half2_rn(f.x, f.y);
        __half2 hi = __floats2half2_rn(f.z, f.w);
        uint2 o;
        o.x = *reinterpret_cast<unsigned*>(&lo);
        o.y = *reinterpret_cast<unsigned*>(&hi);
        reinterpret_cast<uint2*>(g_eh)[i] = o;
    }

    if (tid < PTYPES) g_pexp[tid] = expf(path_w[tid]);
    if (tid == 0) { g_expl = expf(lambda0[0]); g_ovf = 0; }
}

// ---------------------------------------------------------------------------
// 1) scatter — bucket append, 8 edges/thread; streaming loads/stores.
// ---------------------------------------------------------------------------
__device__ __forceinline__ void bkt_put(int row, int pk) {
    int pos = atomicAdd(&g_cnt[row], 1);
    if (pos < CAP) {
        __stcs(&g_bkt[row * CAP + pos], pk);
    } else {                          // adversarial-degree spill (never for bench input)
        int s = atomicAdd(&g_ovf, 1);
        g_sp_row[s] = row;
        g_sp_pk[s]  = pk;
    }
}

__global__ void k_scatter(const int* __restrict__ indices,
                          const int* __restrict__ ptype, int n_edges) {
    int t = blockIdx.x * blockDim.x + threadIdx.x;
    int base = t * 8;
    if (base + 8 <= n_edges) {
        int4 r0 = __ldcs(reinterpret_cast<const int4*>(indices) + t * 2);
        int4 r1 = __ldcs(reinterpret_cast<const int4*>(indices) + t * 2 + 1);
        int4 c0 = __ldcs(reinterpret_cast<const int4*>(indices + n_edges) + t * 2);
        int4 c1 = __ldcs(reinterpret_cast<const int4*>(indices + n_edges) + t * 2 + 1);
        int4 p0 = __ldcs(reinterpret_cast<const int4*>(ptype) + t * 2);
        int4 p1 = __ldcs(reinterpret_cast<const int4*>(ptype) + t * 2 + 1);
        bkt_put(r0.x, c0.x | (p0.x << 24));
        bkt_put(r0.y, c0.y | (p0.y << 24));
        bkt_put(r0.z, c0.z | (p0.z << 24));
        bkt_put(r0.w, c0.w | (p0.w << 24));
        bkt_put(r1.x, c1.x | (p1.x << 24));
        bkt_put(r1.y, c1.y | (p1.y << 24));
        bkt_put(r1.z, c1.z | (p1.z << 24));
        bkt_put(r1.w, c1.w | (p1.w << 24));
    } else {
        for (int e = base; e < n_edges; e++) {
            int row = __ldg(indices + e);
            int col = __ldg(indices + n_edges + e);
            int pt  = __ldg(ptype + e);
            bkt_put(row, col | (pt << 24));
        }
    }
}

// ---------------------------------------------------------------------------
// 2) fused: warp per row, half-warp per edge, one sweep, 4 edges/iter.
//    Streaming data (q, bucket, out) uses evict-first; fp16 tables default.
// ---------------------------------------------------------------------------
__device__ __forceinline__ float dot8h(float4 qa, float4 qb, uint4 kr) {
    float2 k0 = __half22float2(*reinterpret_cast<__half2*>(&kr.x));
    float2 k1 = __half22float2(*reinterpret_cast<__half2*>(&kr.y));
    float2 k2 = __half22float2(*reinterpret_cast<__half2*>(&kr.z));
    float2 k3 = __half22float2(*reinterpret_cast<__half2*>(&kr.w));
    return qa.x * k0.x + qa.y * k0.y + qa.z * k1.x + qa.w * k1.y
         + qb.x * k2.x + qb.y * k2.y + qb.z * k3.x + qb.w * k3.y;
}

__global__ void __launch_bounds__(256)
k_fused(const float* __restrict__ q, float* __restrict__ out, int n_nodes) {
    __shared__ float s_pexp[PTYPES];
    if (threadIdx.x < PTYPES) s_pexp[threadIdx.x] = g_pexp[threadIdx.x];
    __syncthreads();

    int warp = (blockIdx.x * blockDim.x + threadIdx.x) >> 5;
    int lane = threadIdx.x & 31;
    if (warp >= n_nodes) return;
    const int row  = warp;
    const int half = lane >> 4;
    const int hl   = lane & 15;
    const int cnt  = g_cnt[row];
    const int deg  = cnt < CAP ? cnt : CAP;
    const int beg  = row * CAP;
    const int end  = beg + deg;
    const int ovf  = g_ovf;          // 0 for the bench input

    float acc0[8] = {0,0,0,0,0,0,0,0};
    float acc1[8] = {0,0,0,0,0,0,0,0};
    float d0 = 0.f, d1 = 0.f;
    float res[8];

    if (deg > 0 || ovf > 0) {
        const float inv_sqrt_h = 0.08838834764831845f;  // 1/sqrt(128)
        const float* qrow = q + (size_t)row * HDIM + hl * 8;
        float4 qa = __ldcs(reinterpret_cast<const float4*>(qrow));
        float4 qb = __ldcs(reinterpret_cast<const float4*>(qrow) + 1);
        qa.x *= inv_sqrt_h; qa.y *= inv_sqrt_h; qa.z *= inv_sqrt_h; qa.w *= inv_sqrt_h;
        qb.x *= inv_sqrt_h; qb.y *= inv_sqrt_h; qb.z *= inv_sqrt_h; qb.w *= inv_sqrt_h;
        float er = g_expl * __half2float(__ldg(g_eh + (size_t)row * EDIM + hl));

        int j = beg;
        for (; j + 4 <= end; j += 4) {
            int j0 = j + half;
            int j1 = j + 2 + half;
            int pk0 = __ldcs(g_bkt + j0);
            int pk1 = __ldcs(g_bkt + j1);
            int c0 = pk0 & 0xFFFFFF, c1 = pk1 & 0xFFFFFF;
            uint4 kr0 = __ldg(reinterpret_cast<const uint4*>(g_kh + (size_t)c0 * HDIM + hl * 8));
            uint4 kr1 = __ldg(reinterpret_cast<const uint4*>(g_kh + (size_t)c1 * HDIM + hl * 8));
            uint4 vr0 = __ldg(reinterpret_cast<const uint4*>(g_vh + (size_t)c0 * HDIM + hl * 8));
            uint4 vr1 = __ldg(reinterpret_cast<const uint4*>(g_vh + (size_t)c1 * HDIM + hl * 8));
            float ec0 = __half2float(__ldg(g_eh + (size_t)c0 * EDIM + hl));
            float ec1 = __half2float(__ldg(g_eh + (size_t)c1 * EDIM + hl));

            float z0 = dot8h(qa, qb, kr0) + er * ec0;
            float z1 = dot8h(qa, qb, kr1) + er * ec1;
            #pragma unroll
            for (int o = 8; o > 0; o >>= 1) {
                z0 += __shfl_xor_sync(0xffffffffu, z0, o);
                z1 += __shfl_xor_sync(0xffffffffu, z1, o);
            }
            float e00 = __expf(z0);
            float e01 = __expf(z1);
            float pw0 = s_pexp[((unsigned)pk0) >> 24];
            float pw1 = s_pexp[((unsigned)pk1) >> 24];
            d0 += e00 + e01;
            d1 += pw0 + pw1;

            float2 v0[4], v1[4];
            v0[0] = __half22float2(*reinterpret_cast<__half2*>(&vr0.x));
            v0[1] = __half22float2(*reinterpret_cast<__half2*>(&vr0.y));
            v0[2] = __half22float2(*reinterpret_cast<__half2*>(&vr0.z));
            v0[3] = __half22float2(*reinterpret_cast<__half2*>(&vr0.w));
            v1[0] = __half22float2(*reinterpret_cast<__half2*>(&vr1.x));
            v1[1] = __half22float2(*reinterpret_cast<__half2*>(&vr1.y));
            v1[2] = __half22float2(*reinterpret_cast<__half2*>(&vr1.z));
            v1[3] = __half22float2(*reinterpret_cast<__half2*>(&vr1.w));
            #pragma unroll
            for (int i = 0; i < 4; i++) {
                acc0[2*i]   += e00 * v0[i].x + e01 * v1[i].x;
                acc0[2*i+1] += e00 * v0[i].y + e01 * v1[i].y;
                acc1[2*i]   += pw0 * v0[i].x + pw1 * v1[i].x;
                acc1[2*i+1] += pw0 * v0[i].y + pw1 * v1[i].y;
            }
        }
        for (; j < end; j += 2) {
            int jj = j + half;
            bool valid = jj < end;
            int pk0 = __ldcs(g_bkt + (valid ? jj : beg));
            int c0 = pk0 & 0xFFFFFF;
            uint4 kr0 = __ldg(reinterpret_cast<const uint4*>(g_kh + (size_t)c0 * HDIM + hl * 8));
            uint4 vr0 = __ldg(reinterpret_cast<const uint4*>(g_vh + (size_t)c0 * HDIM + hl * 8));
            float ec0 = __half2float(__ldg(g_eh + (size_t)c0 * EDIM + hl));
            float z0 = dot8h(qa, qb, kr0) + er * ec0;
            #pragma unroll
            for (int o = 8; o > 0; o >>= 1)
                z0 += __shfl_xor_sync(0xffffffffu, z0, o);
            float e00 = valid ? __expf(z0) : 0.f;
            float pw0 = valid ? s_pexp[((unsigned)pk0) >> 24] : 0.f;
            d0 += e00;
            d1 += pw0;
            float2 v0[4];
            v0[0] = __half22float2(*reinterpret_cast<__half2*>(&vr0.x));
            v0[1] = __half22float2(*reinterpret_cast<__half2*>(&vr0.y));
            v0[2] = __half22float2(*reinterpret_cast<__half2*>(&vr0.z));
            v0[3] = __half22float2(*reinterpret_cast<__half2*>(&vr0.w));
            #pragma unroll
            for (int i = 0; i < 4; i++) {
                acc0[2*i]   += e00 * v0[i].x;
                acc0[2*i+1] += e00 * v0[i].y;
                acc1[2*i]   += pw0 * v0[i].x;
                acc1[2*i+1] += pw0 * v0[i].y;
            }
        }

        // spill entries (only when some row exceeded CAP; never for bench input)
        for (int s = 0; s < ovf; s++) {
            if (g_sp_row[s] != row) continue;
            int pk0 = g_sp_pk[s];
            int c0 = pk0 & 0xFFFFFF;
            uint4 kr0 = __ldg(reinterpret_cast<const uint4*>(g_kh + (size_t)c0 * HDIM + hl * 8));
            uint4 vr0 = __ldg(reinterpret_cast<const uint4*>(g_vh + (size_t)c0 * HDIM + hl * 8));
            float ec0 = __half2float(__ldg(g_eh + (size_t)c0 * EDIM + hl));
            float z0 = dot8h(qa, qb, kr0) + er * ec0;
            #pragma unroll
            for (int o = 8; o > 0; o >>= 1)
                z0 += __shfl_xor_sync(0xffffffffu, z0, o);
            bool act = (half == 0);      // count each spill edge once
            float e00 = act ? __expf(z0) : 0.f;
            float pw0 = act ? s_pexp[((unsigned)pk0) >> 24] : 0.f;
            d0 += e00;
            d1 += pw0;
            float2 v0[4];
            v0[0] = __half22float2(*reinterpret_cast<__half2*>(&vr0.x));
            v0[1] = __half22float2(*reinterpret_cast<__half2*>(&vr0.y));
            v0[2] = __half22float2(*reinterpret_cast<__half2*>(&vr0.z));
            v0[3] = __half22float2(*reinterpret_cast<__half2*>(&vr0.w));
            #pragma unroll
            for (int i = 0; i < 4; i++) {
                acc0[2*i]   += e00 * v0[i].x;
                acc0[2*i+1] += e00 * v0[i].y;
                acc1[2*i]   += pw0 * v0[i].x;
                acc1[2*i+1] += pw0 * v0[i].y;
            }
        }

        // combine halves and normalize
        d0 += __shfl_xor_sync(0xffffffffu, d0, 16);
        d1 += __shfl_xor_sync(0xffffffffu, d1, 16);
        float i0 = (d0 != 0.f) ? 0.5f / d0 : 0.f;
        float i1 = (d1 != 0.f) ? 0.5f / d1 : 0.f;
        #pragma unroll
        for (int i = 0; i < 8; i++) {
            acc0[i] += __shfl_xor_sync(0xffffffffu, acc0[i], 16);
            acc1[i] += __shfl_xor_sync(0xffffffffu, acc1[i], 16);
            res[i] = i0 * acc0[i] + i1 * acc1[i];
        }
    } else {
        #pragma unroll
        for (int i = 0; i < 8; i++) res[i] = 0.f;
    }

    if (half == 0) {
        float4* o = reinterpret_cast<float4*>(out + (size_t)row * HDIM + hl * 8);
        __stcs(o,     make_float4(res[0], res[1], res[2], res[3]));
        __stcs(o + 1, make_float4(res[4], res[5], res[6], res[7]));
    }
}

// ---------------------------------------------------------------------------
extern "C" void kernel_launch(void* const* d_in, const int* in_sizes, int n_in,
                              void* d_out, int out_size) {
    const float* q       = (const float*)d_in[0];
    const float* k       = (const float*)d_in[1];
    const float* v       = (const float*)d_in[2];
    const float* eigs    = (const float*)d_in[3];
    const float* lambda0 = (const float*)d_in[4];
    const float* path_w  = (const float*)d_in[5];
    const int*   indices = (const int*)d_in[6];
    const int*   ptype   = (const int*)d_in[7];
    float*       out     = (float*)d_out;

    int n_edges = in_sizes[6] / 2;
    int n_nodes = in_sizes[0] / HDIM;
    if (n_edges > EDGES)  n_edges = EDGES;
    if (n_nodes > NNODES) n_nodes = NNODES;

    int eb8 = (n_edges / 8 + 255) / 256 + 1;
    int rb  = (n_nodes * 32 + 255) / 256;

    k_prep<<<2048, 256>>>(k, v, eigs, lambda0, path_w, n_nodes);
    k_scatter<<<eb8, 256>>>(indices, ptype, n_edges);
    k_fused<<<rb, 256>>>(q, out, n_nodes);
}